// round 3
// baseline (speedup 1.0000x reference)
#include <cuda_runtime.h>

// RegLSTM split into two kernels.
// K1 (recurrence): 1 warp = 1 batch element; lane G*8+k owns gate G of hidden
//   unit k. Per step: width-8 h-allgather (8 SHFL), 8-FMA gate projection,
//   one merged activation (ex2/rcp, pre-scaled weights), 3-SHFL gate gather,
//   redundant cell update on all lanes. h_t streamed to a global scratch.
//   2098 warps -> ~3.5 warps/SMSP (vs 0.9 before): latency finally hidden.
// K2 (head): y = W2*tanh(W1 h + b1) + b2 over B*T independent rows, 8 lanes
//   per row, grid-stride; memory-bound (~155MB traffic).

#define B_   2098
#define T_   2048
#define L2E_ 1.4426950408889634f

__device__ float g_hbuf[(size_t)B_ * T_ * 8];   // [B, T, 8] f32 scratch (137.5 MB)

__device__ __forceinline__ float ex2a(float x) {
    float r; asm("ex2.approx.f32 %0, %1;" : "=f"(r) : "f"(x)); return r;
}
__device__ __forceinline__ float rcpa(float x) {
    float r; asm("rcp.approx.f32 %0, %1;" : "=f"(r) : "f"(x)); return r;
}

// ---------------- Kernel 1: LSTM recurrence ----------------
__global__ __launch_bounds__(128) void lstm_kernel(
    const float* __restrict__ x,      // [B, T, 3]
    const float* __restrict__ W_ih,   // [32, 3]
    const float* __restrict__ W_hh,   // [32, 8]
    const float* __restrict__ b_ih,   // [32]
    const float* __restrict__ b_hh)   // [32]
{
    const int tid  = threadIdx.x;
    const int warp = tid >> 5;
    const int g    = blockIdx.x * 4 + warp;         // one element per warp
    if (g >= B_) return;
    const int lane = tid & 31;
    const int G    = lane >> 3;                     // gate: 0=i 1=f 2=g 3=o
    const int kk   = lane & 7;                      // hidden unit
    const unsigned FULL = 0xFFFFFFFFu;

    // pre-scaled weights for this lane's gate row (sigmoid: -L2E, tanh-gate: -2L2E)
    const float sc  = (G == 2) ? (-2.0f * L2E_) : (-L2E_);
    const int  row  = G * 8 + kk;
    const float wi0 = sc * W_ih[row * 3 + 0];
    const float wi1 = sc * W_ih[row * 3 + 1];
    const float wi2 = sc * W_ih[row * 3 + 2];
    const float bsv = sc * (b_ih[row] + b_hh[row]);
    float whh[8];
    #pragma unroll
    for (int j = 0; j < 8; j++) whh[j] = sc * W_hh[row * 8 + j];

    const float* __restrict__ xr = x + (size_t)g * T_ * 3;
    float* __restrict__ hrow = g_hbuf + (size_t)g * T_ * 8;

    float h = 0.0f, cl = 0.0f;   // cl = -2*L2E*c (log-domain cell)

    for (int it = 0; it < T_ / 8; it++) {
        // 8 steps of x: 24 floats, same addresses warp-wide (L1 broadcast)
        const float4* __restrict__ xv = (const float4*)(xr + it * 24);
        const float4 q0 = xv[0], q1 = xv[1], q2 = xv[2], q3 = xv[3], q4 = xv[4], q5 = xv[5];
        float gx[8];
        gx[0] = fmaf(wi0, q0.x, fmaf(wi1, q0.y, fmaf(wi2, q0.z, bsv)));
        gx[1] = fmaf(wi0, q0.w, fmaf(wi1, q1.x, fmaf(wi2, q1.y, bsv)));
        gx[2] = fmaf(wi0, q1.z, fmaf(wi1, q1.w, fmaf(wi2, q2.x, bsv)));
        gx[3] = fmaf(wi0, q2.y, fmaf(wi1, q2.z, fmaf(wi2, q2.w, bsv)));
        gx[4] = fmaf(wi0, q3.x, fmaf(wi1, q3.y, fmaf(wi2, q3.z, bsv)));
        gx[5] = fmaf(wi0, q3.w, fmaf(wi1, q4.x, fmaf(wi2, q4.y, bsv)));
        gx[6] = fmaf(wi0, q4.z, fmaf(wi1, q4.w, fmaf(wi2, q5.x, bsv)));
        gx[7] = fmaf(wi0, q5.y, fmaf(wi1, q5.z, fmaf(wi2, q5.w, bsv)));

        #pragma unroll
        for (int s = 0; s < 8; s++) {
            // h_{t-1} allgather within the lane's 8-lane subgroup
            float hj[8];
            #pragma unroll
            for (int j = 0; j < 8; j++) hj[j] = __shfl_sync(FULL, h, j, 8);

            // gate pre-activation: two 4-FMA chains + add
            float a0 = fmaf(whh[3], hj[3], fmaf(whh[2], hj[2],
                       fmaf(whh[1], hj[1], fmaf(whh[0], hj[0], gx[s]))));
            float a1 = fmaf(whh[7], hj[7], fmaf(whh[6], hj[6],
                       fmaf(whh[5], hj[5], whh[4] * hj[4])));
            const float pre = a0 + a1;

            // act = rcp(1+ex2(pre)): sigmoid for i,f,o; (tanh+1)/2 for g
            const float act = rcpa(1.0f + ex2a(pre));

            // gather all 4 gates of unit kk (redundant on every lane)
            const float si = __shfl_sync(FULL, act, kk,      32);
            const float sf = __shfl_sync(FULL, act, kk + 8,  32);
            const float sg = __shfl_sync(FULL, act, kk + 16, 32);
            const float so = __shfl_sync(FULL, act, kk + 24, 32);

            // cell in log domain: gv' = -2L2E*tanh(g) = fma(-4L2E, sg, 2L2E)
            const float gvp = fmaf(-4.0f * L2E_, sg, 2.0f * L2E_);
            cl = fmaf(sf, cl, si * gvp);

            // h = o * tanh(c) = fma(2o, rcp(1+ex2(cl)), -o)
            const float scc = rcpa(1.0f + ex2a(cl));
            h = fmaf(so + so, scc, -so);

            // stream h_t (lanes 0-7 -> 32B coalesced store)
            if (G == 0) hrow[(it * 8 + s) * 8 + kk] = h;
        }
    }
}

// ---------------- Kernel 2: regression head ----------------
__global__ __launch_bounds__(256) void head_kernel(
    const float* __restrict__ W1,     // [8, 8]
    const float* __restrict__ b1,     // [8]
    const float* __restrict__ W2,     // [1, 8]
    const float* __restrict__ b2,     // [1]
    float* __restrict__ out)          // [B*T]
{
    const int kk = threadIdx.x & 7;
    const unsigned FULL = 0xFFFFFFFFu;
    int group         = (blockIdx.x * blockDim.x + threadIdx.x) >> 3;
    const int ngroups = (gridDim.x * blockDim.x) >> 3;
    const int total   = B_ * T_;

    // z' = -2L2E*(W1 h + b1); tanh(z) = 2*rcp(1+ex2(z')) - 1
    float w1s[8];
    #pragma unroll
    for (int j = 0; j < 8; j++) w1s[j] = (-2.0f * L2E_) * W1[kk * 8 + j];
    const float b1s  = (-2.0f * L2E_) * b1[kk];
    const float w2k2 = 2.0f * W2[kk];
    const float w2kn = -W2[kk];
    const float b2v  = b2[0];

    for (int idx = group; idx < total; idx += ngroups) {
        const float4* __restrict__ hp = (const float4*)(g_hbuf + (size_t)idx * 8);
        const float4 a = hp[0], b = hp[1];
        float za = fmaf(w1s[0], a.x, fmaf(w1s[1], a.y,
                   fmaf(w1s[2], a.z, fmaf(w1s[3], a.w, b1s))));
        float zb = fmaf(w1s[5], b.y, fmaf(w1s[6], b.z,
                   fmaf(w1s[7], b.w, w1s[4] * b.x)));
        const float sz = rcpa(1.0f + ex2a(za + zb));
        float p = fmaf(w2k2, sz, w2kn);
        p += __shfl_xor_sync(FULL, p, 1, 8);
        p += __shfl_xor_sync(FULL, p, 2, 8);
        p += __shfl_xor_sync(FULL, p, 4, 8);
        if (kk == 0) out[idx] = p + b2v;
    }
}

extern "C" void kernel_launch(void* const* d_in, const int* in_sizes, int n_in,
                              void* d_out, int out_size) {
    const float* x    = (const float*)d_in[0];
    const float* W_ih = (const float*)d_in[1];
    const float* W_hh = (const float*)d_in[2];
    const float* b_ih = (const float*)d_in[3];
    const float* b_hh = (const float*)d_in[4];
    const float* W1   = (const float*)d_in[5];
    const float* b1   = (const float*)d_in[6];
    const float* W2   = (const float*)d_in[7];
    const float* b2   = (const float*)d_in[8];
    float* out = (float*)d_out;

    lstm_kernel<<<(B_ + 3) / 4, 128>>>(x, W_ih, W_hh, b_ih, b_hh);
    head_kernel<<<1184, 256>>>(W1, b1, W2, b2, out);
}

// round 6
// speedup vs baseline: 1.4587x; 1.4587x over previous
#include <cuda_runtime.h>

// RegLSTM, single kernel. 16 lanes per element (2 elements/warp, 1049 warps,
// ~2 warps/SMSP). Lane l16 = half*8 + k: half0 owns gates (i, g) of unit k,
// half1 owns (f, o) and the cell/h state.
// Per step MIO budget (the R3 bottleneck): 1 STS + 2 LDS.128 (h exchange via
// double-buffered smem) + 1 shfl (ship p = i*tanh(g) to half1) + 3 shfl (head
// reduce) = 4 SHFL + 3 LDS/STS, vs 12 SHFL in R3.
// All activations (recurrent path AND head) use the exact pre-scaled ex2/rcp
// formulation proven in R1/R2 (no tanh.approx anywhere).

#define B_   2098
#define T_   2048
#define L2E_ 1.4426950408889634f

__device__ __forceinline__ float ex2a(float x) {
    float r; asm("ex2.approx.f32 %0, %1;" : "=f"(r) : "f"(x)); return r;
}
__device__ __forceinline__ float rcpa(float x) {
    float r; asm("rcp.approx.f32 %0, %1;" : "=f"(r) : "f"(x)); return r;
}

__global__ __launch_bounds__(128) void reglstm_kernel(
    const float* __restrict__ x,      // [B, T, 3]
    const float* __restrict__ W_ih,   // [32, 3]  rows: i(0-7) f(8-15) g(16-23) o(24-31)
    const float* __restrict__ W_hh,   // [32, 8]
    const float* __restrict__ b_ih,   // [32]
    const float* __restrict__ b_hh,   // [32]
    const float* __restrict__ W1,     // [8, 8]
    const float* __restrict__ b1,     // [8]
    const float* __restrict__ W2,     // [1, 8]
    const float* __restrict__ b2,     // [1]
    float* __restrict__ out)          // [B, T]
{
    const unsigned FULL = 0xFFFFFFFFu;
    const int tid  = threadIdx.x;
    const int warp = tid >> 5;
    const int g0   = (blockIdx.x * 4 + warp) * 2;   // first element of this warp
    if (g0 >= B_) return;                            // whole-warp exit (B_ even)
    const int lane = tid & 31;
    const int ew   = lane >> 4;                      // element within warp (0/1)
    const int l16  = lane & 15;
    const int half = l16 >> 3;                       // 0: gates i,g   1: gates f,o
    const int k    = l16 & 7;                        // hidden unit
    const int g    = g0 + ew;
    const int eb   = tid >> 4;                       // element within block (0..7)

    // double-buffered h per element: [elem][parity][8]
    __shared__ __align__(16) float sh[8][2][8];

    // ---- lane's two gate rows, pre-scaled ----
    // gate A: half0 -> i (scale -L2E), half1 -> f (-L2E)
    // gate B: half0 -> g (-2L2E),      half1 -> o (-L2E)
    const int rowA = half ? (8 + k)  : k;
    const int rowB = half ? (24 + k) : (16 + k);
    const float scA = -L2E_;
    const float scB = half ? -L2E_ : (-2.0f * L2E_);

    const float wiA0 = scA * W_ih[rowA*3+0], wiA1 = scA * W_ih[rowA*3+1], wiA2 = scA * W_ih[rowA*3+2];
    const float wiB0 = scB * W_ih[rowB*3+0], wiB1 = scB * W_ih[rowB*3+1], wiB2 = scB * W_ih[rowB*3+2];
    const float bA = scA * (b_ih[rowA] + b_hh[rowA]);
    const float bB = scB * (b_ih[rowB] + b_hh[rowB]);
    float whA[8], whB[8];
    #pragma unroll
    for (int j = 0; j < 8; j++) { whA[j] = scA * W_hh[rowA*8+j]; whB[j] = scB * W_hh[rowB*8+j]; }

    // head, pre-scaled (meaningful on half0; harmless elsewhere):
    // z' = -2L2E*(W1 h + b1); tanh(z) = 2*rcp(1+ex2(z')) - 1
    // p = W2[k]*tanh(z) = fma(2*W2[k], sz, -W2[k])
    float w1s[8];
    #pragma unroll
    for (int j = 0; j < 8; j++) w1s[j] = (-2.0f * L2E_) * W1[k*8+j];
    const float b1s  = (-2.0f * L2E_) * b1[k];
    const float w2k2 = 2.0f * W2[k];
    const float w2kn = -W2[k];
    const float b2v  = b2[0];

    const float* __restrict__ xr = x + (size_t)g * T_ * 3;
    float* __restrict__ orow = out + (size_t)g * T_;

    // init h buffer 0 to zeros
    if (half) sh[eb][0][k] = 0.0f;
    __syncwarp();

    float cl = 0.0f, y_keep = 0.0f;   // cl = -2*L2E*c, lives on half1

    // x double buffer (6 float4 per 8 steps)
    const float4* __restrict__ xv = (const float4*)xr;
    float4 c0 = xv[0], c1 = xv[1], c2 = xv[2], c3 = xv[3], c4 = xv[4], c5 = xv[5];

    const int NIT = T_ / 8;
    for (int it = 0; it < NIT; it++) {
        // prefetch next block of x (clamped)
        const int itn = (it + 1 < NIT) ? (it + 1) : it;
        const float4* __restrict__ xn = xv + itn * 6;
        float4 n0 = xn[0], n1 = xn[1], n2 = xn[2], n3 = xn[3], n4 = xn[4], n5 = xn[5];

        const float xs[24] = { c0.x,c0.y,c0.z,c0.w, c1.x,c1.y,c1.z,c1.w,
                               c2.x,c2.y,c2.z,c2.w, c3.x,c3.y,c3.z,c3.w,
                               c4.x,c4.y,c4.z,c4.w, c5.x,c5.y,c5.z,c5.w };
        float gxA[8], gxB[8];
        #pragma unroll
        for (int s = 0; s < 8; s++) {
            gxA[s] = fmaf(wiA0, xs[s*3], fmaf(wiA1, xs[s*3+1], fmaf(wiA2, xs[s*3+2], bA)));
            gxB[s] = fmaf(wiB0, xs[s*3], fmaf(wiB1, xs[s*3+1], fmaf(wiB2, xs[s*3+2], bB)));
        }

        #pragma unroll
        for (int s = 0; s < 8; s++) {
            const int rp = s & 1;           // read parity
            const int wp = rp ^ 1;          // write parity
            // h_{t-1} for this element: 2x LDS.128 broadcast
            const float4 ha = *(const float4*)&sh[eb][rp][0];
            const float4 hb = *(const float4*)&sh[eb][rp][4];

            // ---- head for step t-1 (half0 lanes carry the real value) ----
            {
                float za = fmaf(w1s[0], ha.x, fmaf(w1s[1], ha.y,
                           fmaf(w1s[2], ha.z, fmaf(w1s[3], ha.w, b1s))));
                float zb = fmaf(w1s[5], hb.y, fmaf(w1s[6], hb.z,
                           fmaf(w1s[7], hb.w, w1s[4] * hb.x)));
                const float sz = rcpa(1.0f + ex2a(za + zb));
                float py = fmaf(w2k2, sz, w2kn);
                py += __shfl_xor_sync(FULL, py, 1, 8);
                py += __shfl_xor_sync(FULL, py, 2, 8);
                py += __shfl_xor_sync(FULL, py, 4, 8);
                const float yv = py + b2v;
                const int slot = (s - 1) & 7;          // compile-time
                if (k == slot) y_keep = yv;
            }
            if (s == 0 && it > 0 && !half)
                orow[(it - 1) * 8 + k] = y_keep;       // flush previous 8 outputs

            // ---- gate pre-activations (two 4-FMA chains each) ----
            float aA0 = fmaf(whA[3], ha.w, fmaf(whA[2], ha.z,
                        fmaf(whA[1], ha.y, fmaf(whA[0], ha.x, gxA[s]))));
            float aA1 = fmaf(whA[7], hb.w, fmaf(whA[6], hb.z,
                        fmaf(whA[5], hb.y, whA[4] * hb.x)));
            float aB0 = fmaf(whB[3], ha.w, fmaf(whB[2], ha.z,
                        fmaf(whB[1], ha.y, fmaf(whB[0], ha.x, gxB[s]))));
            float aB1 = fmaf(whB[7], hb.w, fmaf(whB[6], hb.z,
                        fmaf(whB[5], hb.y, whB[4] * hb.x)));
            const float preA = aA0 + aA1;
            const float preB = aB0 + aB1;

            // exact activations: act = rcp(1+ex2(pre))
            // half0: actA=sigm(i), actB=(tanh(g)+1)/2 ; half1: actA=sigm(f), actB=sigm(o)
            const float actA = rcpa(1.0f + ex2a(preA));
            const float actB = rcpa(1.0f + ex2a(preB));

            // half0 computes p = sigm(i) * (-2L2E*tanh(g)); ship to half1
            const float gvp = fmaf(-4.0f * L2E_, actB, 2.0f * L2E_);
            const float p   = actA * gvp;
            const float pr  = __shfl_xor_sync(FULL, p, 8, 16);  // half1 receives half0's p

            // half1: cl = sigm(f)*cl + p ; h = sigm(o)*tanh(c)
            // (half0 lanes compute a contractive dummy recurrence; never stored)
            cl = fmaf(actA, cl, pr);
            const float scc = rcpa(1.0f + ex2a(cl));
            const float h   = fmaf(actB + actB, scc, -actB);

            if (half) sh[eb][wp][k] = h;               // publish h_t
            __syncwarp();
        }

        c0 = n0; c1 = n1; c2 = n2; c3 = n3; c4 = n4; c5 = n5;
    }

    // ---- epilogue: head for t = T-1 (parity: 2048 & 1 == 0 -> buf 0) ----
    {
        const float4 ha = *(const float4*)&sh[eb][0][0];
        const float4 hb = *(const float4*)&sh[eb][0][4];
        float za = fmaf(w1s[0], ha.x, fmaf(w1s[1], ha.y,
                   fmaf(w1s[2], ha.z, fmaf(w1s[3], ha.w, b1s))));
        float zb = fmaf(w1s[5], hb.y, fmaf(w1s[6], hb.z,
                   fmaf(w1s[7], hb.w, w1s[4] * hb.x)));
        const float sz = rcpa(1.0f + ex2a(za + zb));
        float py = fmaf(w2k2, sz, w2kn);
        py += __shfl_xor_sync(FULL, py, 1, 8);
        py += __shfl_xor_sync(FULL, py, 2, 8);
        py += __shfl_xor_sync(FULL, py, 4, 8);
        const float yv = py + b2v;
        if (k == 7) y_keep = yv;
        if (!half) orow[T_ - 8 + k] = y_keep;
    }
}

extern "C" void kernel_launch(void* const* d_in, const int* in_sizes, int n_in,
                              void* d_out, int out_size) {
    const float* x    = (const float*)d_in[0];
    const float* W_ih = (const float*)d_in[1];
    const float* W_hh = (const float*)d_in[2];
    const float* b_ih = (const float*)d_in[3];
    const float* b_hh = (const float*)d_in[4];
    const float* W1   = (const float*)d_in[5];
    const float* b1   = (const float*)d_in[6];
    const float* W2   = (const float*)d_in[7];
    const float* b2   = (const float*)d_in[8];
    float* out = (float*)d_out;

    // 2 elements/warp, 8/block -> 263 blocks (last block: 1 idle warp)
    const int grid = (B_ + 7) / 8;
    reglstm_kernel<<<grid, 128>>>(x, W_ih, W_hh, b_ih, b_hh, W1, b1, W2, b2, out);
}